// round 16
// baseline (speedup 1.0000x reference)
#include <cuda_runtime.h>
#include <cuda_fp16.h>
#include <cstdint>

#define NROW 12288
#define INF  128
#define OUTF 64
#define LOG2E 1.44269504088896341f
#define NCHUNK 3
#define CT 32                      // tiles per chunk (32*128 = 4096 cols)
#define NITILE (NROW / 128)        // 96
#define NUNITS (NITILE * NCHUNK)   // 288 == grid
#define KCMAX (CT * 8)             // 256 k-chunks per unit

// smem offsets
#define B0o  0
#define B1o  16384
#define WH2S 32768
#define SMEM_BYTES 49152

// ---------------- device scratch ----------------
__device__ float  g_wh1[NROW];
__device__ float  g_wh2[NROW];
__device__ float  g_wh2max;
// h transposed fp16 [f][j], j PRE-PERMUTED into mma k-slot order:
// within each 16-j group, j=16g+4c+e -> p=16g+2c+e (e<2) / 16g+8+2c+(e-2)
__device__ __align__(16) __half g_hTp[OUTF * NROW];
__device__ float  g_S[NCHUNK][NROW * OUTF];          // partial E'@h per chunk
__device__ float  g_L[NCHUNK][NROW];                 // row sums per chunk

// ---------------- Kernel A: h = input@W, wh1/wh2, permuted hT ----------------
__global__ void kA(const float* __restrict__ inp, const float* __restrict__ W,
                   const float* __restrict__ a) {
    __shared__ float in_s[4][INF];
    __shared__ float red1[8], red2[8];
    int tid = threadIdx.x;
    int i0 = blockIdx.x * 4;
    for (int e = tid; e < 4 * INF; e += 256)
        in_s[e >> 7][e & 127] = inp[(i0 + (e >> 7)) * INF + (e & 127)];
    __syncthreads();
    int f = tid & 63, r = tid >> 6;
    float acc = 0.f;
#pragma unroll 8
    for (int k = 0; k < INF; k++)
        acc = fmaf(in_s[r][k], W[k * OUTF + f], acc);
    int i = i0 + r;
    {   // permuted position
        int g = i >> 4, rr = i & 15;
        int c = rr >> 2, e = rr & 3;
        int p = g * 16 + ((e < 2) ? (2 * c + e) : (8 + 2 * c + (e - 2)));
        g_hTp[f * NROW + p] = __float2half(acc);
    }
    float p1 = acc * a[f];
    float p2 = acc * a[64 + f];
#pragma unroll
    for (int o = 16; o > 0; o >>= 1) {
        p1 += __shfl_xor_sync(~0u, p1, o);
        p2 += __shfl_xor_sync(~0u, p2, o);
    }
    int w = tid >> 5;
    if ((tid & 31) == 0) { red1[w] = p1; red2[w] = p2; }
    __syncthreads();
    if (tid < 4) {
        g_wh1[i0 + tid] = red1[2 * tid] + red1[2 * tid + 1];
        g_wh2[i0 + tid] = red2[2 * tid] + red2[2 * tid + 1];
    }
}

// ---------------- Kernel A2: global max of wh2 ----------------
__global__ void kMax() {
    __shared__ float red[8];
    int tid = threadIdx.x;
    float m = -1e30f;
    for (int i = tid; i < NROW; i += 256) m = fmaxf(m, g_wh2[i]);
#pragma unroll
    for (int o = 16; o > 0; o >>= 1) m = fmaxf(m, __shfl_xor_sync(~0u, m, o));
    if ((tid & 31) == 0) red[tid >> 5] = m;
    __syncthreads();
    if (tid == 0) {
        float mm = red[0];
#pragma unroll
        for (int w = 1; w < 8; w++) mm = fmaxf(mm, red[w]);
        g_wh2max = mm;
    }
}

// pad so ncu's capture (launch index 3) lands on kMain
__global__ void kPad() {}

__device__ __forceinline__ void cp_async16(uint32_t dst, const void* src) {
    asm volatile("cp.async.cg.shared.global [%0], [%1], 16;\n" :: "r"(dst), "l"(src));
}

// ---------------- Kernel B: R10 structure + cp.async B + depth-4 adj prefetch ----------------
// 256 threads, 2 CTAs/SM. Warp w owns rows i0 + w*16 .. +15 (2 streams: rA, rA+8),
// all k-slots of every tile. E' built directly in mma A-fragment registers.
__global__ void __launch_bounds__(256, 2) kMain(const int* __restrict__ adj) {
    extern __shared__ char smem[];
    uint32_t sb = (uint32_t)__cvta_generic_to_shared(smem);
    float* wh2s = (float*)(smem + WH2S);
    int tid = threadIdx.x, lane = tid & 31, w = tid >> 5;

    int u = blockIdx.x;
    int itile = u / NCHUNK, chunk = u % NCHUNK;
    int i0 = itile * 128;
    long long jbase = (long long)chunk * (CT * 128);

    // stage this unit's wh2 (4096 floats = 16KB)
    {
        const float4* src = (const float4*)(g_wh2 + jbase);
        float4* dst = (float4*)wh2s;
#pragma unroll
        for (int k = 0; k < 4; k++) dst[tid + k * 256] = src[tid + k * 256];
    }

    // cp.async B mapping (R15-proven): thread -> row bn=tid>>2, 4 x 16B units
    int bn = tid >> 2;
    int bu0 = (tid & 3) * 4;
    uint32_t bnx = (uint32_t)((bn & 7) << 1);
    const char* bsrc = (const char*)g_hTp + ((size_t)bn * NROW + (size_t)jbase) * 2 + bu0 * 16;
    uint32_t bdst_row = (uint32_t)(bn * 256);
#pragma unroll
    for (int k = 0; k < 4; k++)
        cp_async16(sb + B0o + bdst_row + ((uint32_t)((bu0 + k) ^ bnx) << 4), bsrc + k * 16);
    asm volatile("cp.async.commit_group;");

    // per-lane row constants (rows rA, rA+8)
    int rA = i0 + w * 16 + (lane >> 2);
    const float wh2max = g_wh2max;
    float w1a = g_wh1[rA], w1b = g_wh1[rA + 8];
    float sA = w1a + wh2max, sB = w1b + wh2max;
    float m2a = fmaxf(sA, 0.2f * sA) * LOG2E;    // lrelu upper bound of row max
    float m2b = fmaxf(sB, 0.2f * sB) * LOG2E;

    // adj streams, depth-4 rolling prefetch
    const int* pA = adj + (long long)rA * NROW + jbase + (lane & 3) * 4;
    const int* pB = pA + (long long)8 * NROW;
    int4 avA[4], avB[4];
#pragma unroll
    for (int d = 0; d < 4; d++) {
        avA[d] = __ldcs((const int4*)(pA + d * 16));
        avB[d] = __ldcs((const int4*)(pB + d * 16));
    }

    // B ldmatrix constants (R10-proven)
    int g2 = lane >> 4, kh = (lane >> 3) & 1, r7 = lane & 7;
    uint32_t bxor = (uint32_t)(r7 << 1);
    uint32_t Bb2off = (uint32_t)((g2 * 8 + r7) * 256);

    float acc[8][4];
#pragma unroll
    for (int nt = 0; nt < 8; nt++)
#pragma unroll
        for (int q = 0; q < 4; q++) acc[nt][q] = 0.f;
    float fr0 = 0.f, fr8 = 0.f;

    __syncthreads();   // wh2s staged

    for (int t = 0; t < CT; t++) {
        uint32_t Bbuf = sb + ((t & 1) ? B1o : B0o);
        asm volatile("cp.async.wait_group 0;");
        __syncthreads();   // B(t) visible; all warps done with B(t-1)'s buffer

        if (t + 1 < CT) {  // prefetch B(t+1) into the other buffer
            const char* src = bsrc + (t + 1) * 256;
            uint32_t dstb = sb + (((t + 1) & 1) ? B1o : B0o) + bdst_row;
#pragma unroll
            for (int k = 0; k < 4; k++)
                cp_async16(dstb + ((uint32_t)((bu0 + k) ^ bnx) << 4), src + k * 16);
            asm volatile("cp.async.commit_group;");
        }

#pragma unroll
        for (int ks = 0; ks < 8; ks++) {
            int kcg = t * 8 + ks;
            int d = kcg & 3;
            // clamped depth-4 prefetch (tail reads wrap to 0; values unused)
            int kpf = (kcg + 4 < KCMAX) ? (kcg + 4) : 0;
            int4 aR = avA[d], aR8 = avB[d];
            avA[d] = __ldcs((const int4*)(pA + kpf * 16));
            avB[d] = __ldcs((const int4*)(pB + kpf * 16));
            float4 wv = *(const float4*)(wh2s + kcg * 16 + (lane & 3) * 4);

            // E' directly in mma A-fragment layout (permuted k-slots)
            float s0 = w1a + wv.x, s1 = w1a + wv.y, s2 = w1a + wv.z, s3 = w1a + wv.w;
            float u0 = w1b + wv.x, u1 = w1b + wv.y, u2 = w1b + wv.z, u3 = w1b + wv.w;
            float x0 = fmaf(fmaxf(s0, 0.2f * s0), LOG2E, -m2a);
            float x1 = fmaf(fmaxf(s1, 0.2f * s1), LOG2E, -m2a);
            float x2 = fmaf(fmaxf(s2, 0.2f * s2), LOG2E, -m2a);
            float x3 = fmaf(fmaxf(s3, 0.2f * s3), LOG2E, -m2a);
            float y0 = fmaf(fmaxf(u0, 0.2f * u0), LOG2E, -m2b);
            float y1 = fmaf(fmaxf(u1, 0.2f * u1), LOG2E, -m2b);
            float y2 = fmaf(fmaxf(u2, 0.2f * u2), LOG2E, -m2b);
            float y3 = fmaf(fmaxf(u3, 0.2f * u3), LOG2E, -m2b);
            x0 = aR.x ? x0 : -1e4f;  x1 = aR.y ? x1 : -1e4f;
            x2 = aR.z ? x2 : -1e4f;  x3 = aR.w ? x3 : -1e4f;
            y0 = aR8.x ? y0 : -1e4f; y1 = aR8.y ? y1 : -1e4f;
            y2 = aR8.z ? y2 : -1e4f; y3 = aR8.w ? y3 : -1e4f;
            __half2 hx01 = __floats2half2_rn(x0, x1);
            __half2 hx23 = __floats2half2_rn(x2, x3);
            __half2 hy01 = __floats2half2_rn(y0, y1);
            __half2 hy23 = __floats2half2_rn(y2, y3);
            uint32_t a0, a1, a2, a3;
            asm("ex2.approx.f16x2 %0, %1;" : "=r"(a0) : "r"(*(uint32_t*)&hx01));
            asm("ex2.approx.f16x2 %0, %1;" : "=r"(a1) : "r"(*(uint32_t*)&hy01));
            asm("ex2.approx.f16x2 %0, %1;" : "=r"(a2) : "r"(*(uint32_t*)&hx23));
            asm("ex2.approx.f16x2 %0, %1;" : "=r"(a3) : "r"(*(uint32_t*)&hy23));

            // row sums (pairwise half add, exact float accumulate)
            {
                __half2 hr0 = __hadd2(*(__half2*)&a0, *(__half2*)&a2);
                __half2 hr8 = __hadd2(*(__half2*)&a1, *(__half2*)&a3);
                float2 f0 = __half22float2(hr0);
                float2 f8 = __half22float2(hr8);
                fr0 += f0.x + f0.y;
                fr8 += f8.x + f8.y;
            }

            // B fragments + 8 MMAs
            uint32_t bsw = (((uint32_t)(ks * 2 + kh)) ^ bxor) << 4;
            uint32_t Bb = Bbuf + Bb2off + bsw;
#pragma unroll
            for (int nt2 = 0; nt2 < 4; nt2++) {
                uint32_t b0, b1, b2, b3;
                asm volatile("ldmatrix.sync.aligned.m8n8.x4.shared.b16 {%0,%1,%2,%3}, [%4];"
                             : "=r"(b0), "=r"(b1), "=r"(b2), "=r"(b3)
                             : "r"(Bb + (uint32_t)(nt2 * 4096)));
                int nt = nt2 * 2;
                asm volatile("mma.sync.aligned.m16n8k16.row.col.f32.f16.f16.f32 "
                             "{%0,%1,%2,%3}, {%4,%5,%6,%7}, {%8,%9}, {%0,%1,%2,%3};"
                             : "+f"(acc[nt][0]), "+f"(acc[nt][1]),
                               "+f"(acc[nt][2]), "+f"(acc[nt][3])
                             : "r"(a0), "r"(a1), "r"(a2), "r"(a3), "r"(b0), "r"(b1));
                asm volatile("mma.sync.aligned.m16n8k16.row.col.f32.f16.f16.f32 "
                             "{%0,%1,%2,%3}, {%4,%5,%6,%7}, {%8,%9}, {%0,%1,%2,%3};"
                             : "+f"(acc[nt + 1][0]), "+f"(acc[nt + 1][1]),
                               "+f"(acc[nt + 1][2]), "+f"(acc[nt + 1][3])
                             : "r"(a0), "r"(a1), "r"(a2), "r"(a3), "r"(b2), "r"(b3));
            }
        }
    }

    // ---------------- writeback ----------------
    {
        int row0 = i0 + w * 16 + (lane >> 2);
        int colb = (lane & 3) * 2;
        float* Sp = g_S[chunk];
#pragma unroll
        for (int nt = 0; nt < 8; nt++) {
            *(float2*)(Sp + row0 * OUTF + nt * 8 + colb) =
                make_float2(acc[nt][0], acc[nt][1]);
            *(float2*)(Sp + (row0 + 8) * OUTF + nt * 8 + colb) =
                make_float2(acc[nt][2], acc[nt][3]);
        }
    }
    // row sums: reduce within c-quad
    fr0 += __shfl_xor_sync(~0u, fr0, 1);
    fr0 += __shfl_xor_sync(~0u, fr0, 2);
    fr8 += __shfl_xor_sync(~0u, fr8, 1);
    fr8 += __shfl_xor_sync(~0u, fr8, 2);
    if ((lane & 3) == 0) {
        g_L[chunk][rA] = fr0;
        g_L[chunk][rA + 8] = fr8;
    }
}

// ---------------- Kernel C: reduce chunks, normalize + ELU ----------------
__global__ void kEpi(float* __restrict__ out) {
    int idx = blockIdx.x * 256 + threadIdx.x;   // NROW*64
    int i = idx >> 6, f = idx & 63;
    float l = 0.f, v = 0.f;
#pragma unroll
    for (int c = 0; c < NCHUNK; c++) {
        l += g_L[c][i];
        v += g_S[c][i * OUTF + f];
    }
    v /= l;
    out[idx] = v > 0.f ? v : expm1f(v);
}

// ---------------- launch ----------------
extern "C" void kernel_launch(void* const* d_in, const int* in_sizes, int n_in,
                              void* d_out, int out_size) {
    (void)in_sizes; (void)n_in; (void)out_size;
    const float* inp = (const float*)d_in[0];
    const int*   adj = (const int*)d_in[1];
    const float* W   = (const float*)d_in[2];
    const float* a   = (const float*)d_in[3];

    cudaFuncSetAttribute(kMain, cudaFuncAttributeMaxDynamicSharedMemorySize, SMEM_BYTES);

    kA<<<NROW / 4, 256>>>(inp, W, a);           // index 0
    kMax<<<1, 256>>>();                         // index 1
    kPad<<<1, 32>>>();                          // index 2
    kMain<<<NUNITS, 256, SMEM_BYTES>>>(adj);    // index 3  <- ncu capture
    kEpi<<<NROW * OUTF / 256, 256>>>((float*)d_out);
}

// round 17
// speedup vs baseline: 1.1604x; 1.1604x over previous
#include <cuda_runtime.h>
#include <cuda_fp16.h>
#include <cstdint>

#define NROW 12288
#define INF  128
#define OUTF 64
#define LOG2E 1.44269504088896341f
#define NCHUNK 3
#define CT 32                      // tiles per chunk (32*128 = 4096 cols)
#define NITILE (NROW / 128)        // 96
#define NUNITS (NITILE * NCHUNK)   // 288 == grid
#define KC_MAX (CT * 8)            // 256 k-chunks per unit

// smem offsets (dynamic, per CTA)
#define B0 0
#define B1 16384
#define WH2S 32768
#define SMEM_BYTES 49152

// ---------------- device scratch ----------------
__device__ float  g_wh1[NROW];
__device__ float  g_wh2[NROW];
__device__ unsigned g_wh2maxbits = 0u;               // keyed max (monotone uint key)
__device__ __align__(16) __half g_hT[OUTF * NROW];   // h transposed fp16 [f][j]
__device__ float  g_S[NCHUNK][NROW * OUTF];          // partial E'@h per chunk
__device__ float  g_L[NCHUNK][NROW];                 // partial row sums per chunk

__device__ __forceinline__ unsigned fkey(float f) {
    unsigned b = __float_as_uint(f);
    return (b & 0x80000000u) ? ~b : (b | 0x80000000u);
}
__device__ __forceinline__ float fdec(unsigned k) {
    unsigned b = (k & 0x80000000u) ? (k & 0x7FFFFFFFu) : ~k;
    return __uint_as_float(b);
}

// ---------------- Kernel A: h = input@W, wh1/wh2, hT, fused wh2-max ----------------
__global__ void kA(const float* __restrict__ inp, const float* __restrict__ W,
                   const float* __restrict__ a) {
    __shared__ float in_s[4][INF];
    __shared__ float red1[8], red2[8];
    int tid = threadIdx.x;
    int i0 = blockIdx.x * 4;
    for (int e = tid; e < 4 * INF; e += 256)
        in_s[e >> 7][e & 127] = inp[(i0 + (e >> 7)) * INF + (e & 127)];
    __syncthreads();
    int f = tid & 63, r = tid >> 6;
    float acc = 0.f;
#pragma unroll 8
    for (int k = 0; k < INF; k++)
        acc = fmaf(in_s[r][k], W[k * OUTF + f], acc);
    int i = i0 + r;
    g_hT[f * NROW + i] = __float2half(acc);
    float p1 = acc * a[f];
    float p2 = acc * a[64 + f];
#pragma unroll
    for (int o = 16; o > 0; o >>= 1) {
        p1 += __shfl_xor_sync(~0u, p1, o);
        p2 += __shfl_xor_sync(~0u, p2, o);
    }
    int w = tid >> 5;
    if ((tid & 31) == 0) { red1[w] = p1; red2[w] = p2; }
    __syncthreads();
    if (tid < 4) {
        float v1 = red1[2 * tid] + red1[2 * tid + 1];
        float v2 = red2[2 * tid] + red2[2 * tid + 1];
        g_wh1[i0 + tid] = v1;
        g_wh2[i0 + tid] = v2;
        // block max of the 4 wh2 values -> one atomic per block
        float m = v2;
        m = fmaxf(m, __shfl_xor_sync(0x0000000Fu, m, 1));
        m = fmaxf(m, __shfl_xor_sync(0x0000000Fu, m, 2));
        if (tid == 0) atomicMax(&g_wh2maxbits, fkey(m));
    }
}

// ---------------- Kernel B: homogeneous warps, reg-resident A fragments ----------------
// (R10 champion, byte-identical except wh2max source)
// 256 threads, 2 CTAs/SM. Warp w owns output rows i0 + w*16 .. +15.
// k-slot permutation within each 16-j chunk: slot-word m -> j-word q:
//   q = (m<4) ? 2m : 2(m-4)+1   (so A lanes load adj via one LDG.128 per row)
__global__ void __launch_bounds__(256, 2) kMain(const int* __restrict__ adj) {
    extern __shared__ char smem[];
    uint32_t sb = (uint32_t)__cvta_generic_to_shared(smem);
    float* wh2s = (float*)(smem + WH2S);
    int tid = threadIdx.x, lane = tid & 31, w = tid >> 5;

    int u = blockIdx.x;
    int itile = u / NCHUNK, chunk = u % NCHUNK;
    int i0 = itile * 128;
    long long jbase = (long long)chunk * (CT * 128);

    // stage this unit's wh2 (4096 floats = 16KB)
    {
        const float4* src = (const float4*)(g_wh2 + jbase);
        float4* dst = (float4*)wh2s;
#pragma unroll
        for (int k = 0; k < 4; k++) dst[tid + k * 256] = src[tid + k * 256];
    }

    // per-lane row constants (rows rA, rA+8)
    int rA = i0 + w * 16 + (lane >> 2);
    const float wh2max = fdec(g_wh2maxbits);
    float w1a = g_wh1[rA], w1b = g_wh1[rA + 8];
    float sA = w1a + wh2max, sB = w1b + wh2max;
    float m2a = fmaxf(sA, 0.2f * sA) * LOG2E;    // lrelu upper bound of row max
    float m2b = fmaxf(sB, 0.2f * sB) * LOG2E;

    // adj stream pointers: lane covers j = kc*16 + (lane&3)*4 .. +3
    const int* pA = adj + (long long)rA * NROW + jbase + (lane & 3) * 4;
    const int* pB = pA + (long long)8 * NROW;
    int4 avA[2], avB[2];
    avA[0] = __ldcs((const int4*)(pA));
    avB[0] = __ldcs((const int4*)(pB));
    avA[1] = __ldcs((const int4*)(pA + 16));
    avB[1] = __ldcs((const int4*)(pB + 16));

    // B loader: warp w loads n = w + 8s, jq = lane (uint2 = 2 words = 4 halfs)
    const uint2* hT2 = (const uint2*)g_hT;
    long long bcol0 = (jbase >> 2);
    uint2 bw[8];
#pragma unroll
    for (int s = 0; s < 8; s++)
        bw[s] = __ldg(&hT2[(w + 8 * s) * (NROW / 4) + bcol0 + lane]);

    // permuted slot-word indices for the two words of each uint2
    int jp0 = ((lane >> 2) << 3) | (lane & 3);   // word 2*jq (j even pair): m = q/2
    int jp1 = jp0 + 4;                           // word 2*jq+1 (odd): m = 4 + q/2
    uint32_t st_hi0 = (uint32_t)((jp0 >> 2) << 4);
    uint32_t st_lo0 = (uint32_t)((jp0 & 3) * 4);
    uint32_t st_hi1 = (uint32_t)((jp1 >> 2) << 4);
    uint32_t st_lo1 = (uint32_t)((jp1 & 3) * 4);

    // B ldmatrix constants
    int g2 = lane >> 4, kh = (lane >> 3) & 1, r7 = lane & 7;
    uint32_t brow[4];
#pragma unroll
    for (int nt2 = 0; nt2 < 4; nt2++)
        brow[nt2] = (uint32_t)((nt2 * 16 + g2 * 8 + r7) * 256);
    uint32_t bxor = (uint32_t)(r7 << 1);

    float acc[8][4];
#pragma unroll
    for (int nt = 0; nt < 8; nt++)
#pragma unroll
        for (int q = 0; q < 4; q++) acc[nt][q] = 0.f;
    float fr0 = 0.f, fr8 = 0.f;

    for (int t = 0; t < CT; t++) {
        uint32_t Bbuf = sb + ((t & 1) ? B1 : B0);
        // store B(t) with slot permutation + xor swizzle
#pragma unroll
        for (int s = 0; s < 8; s++) {
            uint32_t n = (uint32_t)(w + 8 * s);
            uint32_t nx = (n & 7) << 1;
            uint32_t base = Bbuf + n * 256;
            uint32_t a0 = base + (((st_hi0 >> 4) ^ nx) << 4) + st_lo0;
            uint32_t a1 = base + (((st_hi1 >> 4) ^ nx) << 4) + st_lo1;
            asm volatile("st.shared.b32 [%0], %1;" :: "r"(a0), "r"(bw[s].x));
            asm volatile("st.shared.b32 [%0], %1;" :: "r"(a1), "r"(bw[s].y));
        }
        __syncthreads();   // B(t) visible; also guarantees all warps done with MMA(t-1)

        // prefetch B(t+1) under this tile's MMA
        if (t + 1 < CT) {
            long long c = bcol0 + (long long)(t + 1) * 32;
#pragma unroll
            for (int s = 0; s < 8; s++)
                bw[s] = __ldg(&hT2[(w + 8 * s) * (NROW / 4) + c + lane]);
        }

#pragma unroll
        for (int ks = 0; ks < 8; ks++) {
            int kc = t * 8 + ks;
            int4 aR = avA[kc & 1], aR8 = avB[kc & 1];
            if (kc + 2 < KC_MAX) {                       // rolling depth-2 adj prefetch
                avA[kc & 1] = __ldcs((const int4*)(pA + (kc + 2) * 16));
                avB[kc & 1] = __ldcs((const int4*)(pB + (kc + 2) * 16));
            }
            float4 wv = *(const float4*)(wh2s + kc * 16 + (lane & 3) * 4);

            // E' directly in mma A-fragment layout (permuted k-slots)
            float s0 = w1a + wv.x, s1 = w1a + wv.y, s2 = w1a + wv.z, s3 = w1a + wv.w;
            float u0 = w1b + wv.x, u1 = w1b + wv.y, u2 = w1b + wv.z, u3 = w1b + wv.w;
            float x0 = fmaf(fmaxf(s0, 0.2f * s0), LOG2E, -m2a);
            float x1 = fmaf(fmaxf(s1, 0.2f * s1), LOG2E, -m2a);
            float x2 = fmaf(fmaxf(s2, 0.2f * s2), LOG2E, -m2a);
            float x3 = fmaf(fmaxf(s3, 0.2f * s3), LOG2E, -m2a);
            float y0 = fmaf(fmaxf(u0, 0.2f * u0), LOG2E, -m2b);
            float y1 = fmaf(fmaxf(u1, 0.2f * u1), LOG2E, -m2b);
            float y2 = fmaf(fmaxf(u2, 0.2f * u2), LOG2E, -m2b);
            float y3 = fmaf(fmaxf(u3, 0.2f * u3), LOG2E, -m2b);
            x0 = aR.x ? x0 : -1e4f;  x1 = aR.y ? x1 : -1e4f;
            x2 = aR.z ? x2 : -1e4f;  x3 = aR.w ? x3 : -1e4f;
            y0 = aR8.x ? y0 : -1e4f; y1 = aR8.y ? y1 : -1e4f;
            y2 = aR8.z ? y2 : -1e4f; y3 = aR8.w ? y3 : -1e4f;
            __half2 hx01 = __floats2half2_rn(x0, x1);
            __half2 hx23 = __floats2half2_rn(x2, x3);
            __half2 hy01 = __floats2half2_rn(y0, y1);
            __half2 hy23 = __floats2half2_rn(y2, y3);
            uint32_t a0, a1, a2, a3;
            asm("ex2.approx.f16x2 %0, %1;" : "=r"(a0) : "r"(*(uint32_t*)&hx01));
            asm("ex2.approx.f16x2 %0, %1;" : "=r"(a1) : "r"(*(uint32_t*)&hy01));
            asm("ex2.approx.f16x2 %0, %1;" : "=r"(a2) : "r"(*(uint32_t*)&hx23));
            asm("ex2.approx.f16x2 %0, %1;" : "=r"(a3) : "r"(*(uint32_t*)&hy23));

            // row-sum accumulation (pairwise half add, then exact float accumulate)
            {
                __half2 hr0 = __hadd2(*(__half2*)&a0, *(__half2*)&a2);
                __half2 hr8 = __hadd2(*(__half2*)&a1, *(__half2*)&a3);
                float2 f0 = __half22float2(hr0);
                float2 f8 = __half22float2(hr8);
                fr0 += f0.x + f0.y;
                fr8 += f8.x + f8.y;
            }

            // B fragments + 8 MMAs
            uint32_t bsw = ((((uint32_t)(ks * 2 + kh)) ^ bxor) << 4);
#pragma unroll
            for (int nt2 = 0; nt2 < 4; nt2++) {
                uint32_t b0, b1, b2, b3;
                asm volatile("ldmatrix.sync.aligned.m8n8.x4.shared.b16 {%0,%1,%2,%3}, [%4];"
                             : "=r"(b0), "=r"(b1), "=r"(b2), "=r"(b3)
                             : "r"(Bbuf + brow[nt2] + bsw));
                int nt = nt2 * 2;
                asm volatile("mma.sync.aligned.m16n8k16.row.col.f32.f16.f16.f32 "
                             "{%0,%1,%2,%3}, {%4,%5,%6,%7}, {%8,%9}, {%0,%1,%2,%3};"
                             : "+f"(acc[nt][0]), "+f"(acc[nt][1]),
                               "+f"(acc[nt][2]), "+f"(acc[nt][3])
                             : "r"(a0), "r"(a1), "r"(a2), "r"(a3), "r"(b0), "r"(b1));
                asm volatile("mma.sync.aligned.m16n8k16.row.col.f32.f16.f16.f32 "
                             "{%0,%1,%2,%3}, {%4,%5,%6,%7}, {%8,%9}, {%0,%1,%2,%3};"
                             : "+f"(acc[nt + 1][0]), "+f"(acc[nt + 1][1]),
                               "+f"(acc[nt + 1][2]), "+f"(acc[nt + 1][3])
                             : "r"(a0), "r"(a1), "r"(a2), "r"(a3), "r"(b2), "r"(b3));
            }
        }
    }

    // ---- writeback accumulators ----
    {
        int row0 = i0 + w * 16 + (lane >> 2);
        int colb = (lane & 3) * 2;
        float* Sp = g_S[chunk];
#pragma unroll
        for (int nt = 0; nt < 8; nt++) {
            *(float2*)(Sp + row0 * OUTF + nt * 8 + colb) =
                make_float2(acc[nt][0], acc[nt][1]);
            *(float2*)(Sp + (row0 + 8) * OUTF + nt * 8 + colb) =
                make_float2(acc[nt][2], acc[nt][3]);
        }
    }
    // ---- row sums: reduce within c-quad ----
    fr0 += __shfl_xor_sync(~0u, fr0, 1);
    fr0 += __shfl_xor_sync(~0u, fr0, 2);
    fr8 += __shfl_xor_sync(~0u, fr8, 1);
    fr8 += __shfl_xor_sync(~0u, fr8, 2);
    if ((lane & 3) == 0) {
        g_L[chunk][rA] = fr0;
        g_L[chunk][rA + 8] = fr8;
    }
}

// ---------------- Kernel C: reduce chunks, normalize + ELU ----------------
__global__ void kEpi(float* __restrict__ out) {
    int idx = blockIdx.x * 256 + threadIdx.x;   // NROW*64
    int i = idx >> 6, f = idx & 63;
    float l = 0.f, v = 0.f;
#pragma unroll
    for (int c = 0; c < NCHUNK; c++) {
        l += g_L[c][i];
        v += g_S[c][i * OUTF + f];
    }
    v /= l;
    out[idx] = v > 0.f ? v : expm1f(v);
}

// ---------------- launch ----------------
extern "C" void kernel_launch(void* const* d_in, const int* in_sizes, int n_in,
                              void* d_out, int out_size) {
    (void)in_sizes; (void)n_in; (void)out_size;
    const float* inp = (const float*)d_in[0];
    const int*   adj = (const int*)d_in[1];
    const float* W   = (const float*)d_in[2];
    const float* a   = (const float*)d_in[3];

    cudaFuncSetAttribute(kMain, cudaFuncAttributeMaxDynamicSharedMemorySize, SMEM_BYTES);

    kA<<<NROW / 4, 256>>>(inp, W, a);           // fused wh2-max (kMax removed)
    kMain<<<NUNITS, 256, SMEM_BYTES>>>(adj);
    kEpi<<<NROW * OUTF / 256, 256>>>((float*)d_out);
}